// round 16
// baseline (speedup 1.0000x reference)
#include <cuda_runtime.h>
#include <cuda_fp16.h>
#include <cstdint>
#include <math.h>

// Shapes (fixed)
constexpr int NROW = 128;
constexpr int DDIM = 512;
constexpr int CDIM = 8192;
constexpr int NQ   = 32768;

// ---------------- device scratch ----------------
__device__ __align__(16) unsigned short g_a1[NROW * DDIM]; // fp16 normalized new_embeds
__device__ __align__(16) unsigned short g_a2[NROW * CDIM]; // fp16 new_logits
__device__ int   g_qlab[NQ];
// per (problem, ctaN, row): m, l, sw, s1w, cnt, pad[3]
__device__ __align__(16) float g_pp[2][256][NROW][8];
__device__ float g_terms[2 * NROW];

// ---------------- small helpers ----------------
__device__ __forceinline__ uint32_t smem_u32(const void* p) {
    uint32_t a;
    asm("{ .reg .u64 t; cvta.to.shared.u64 t, %1; cvt.u32.u64 %0, t; }" : "=r"(a) : "l"(p));
    return a;
}
__device__ __forceinline__ void ldm4(uint32_t* r, uint32_t addr) {
    asm volatile("ldmatrix.sync.aligned.m8n8.x4.shared.b16 {%0,%1,%2,%3}, [%4];"
                 : "=r"(r[0]), "=r"(r[1]), "=r"(r[2]), "=r"(r[3]) : "r"(addr));
}
__device__ __forceinline__ void mma_f16(float* d, const uint32_t* a, const uint32_t* b) {
    asm volatile(
        "mma.sync.aligned.m16n8k16.row.col.f32.f16.f16.f32 "
        "{%0,%1,%2,%3}, {%4,%5,%6,%7}, {%8,%9}, {%0,%1,%2,%3};"
        : "+f"(d[0]), "+f"(d[1]), "+f"(d[2]), "+f"(d[3])
        : "r"(a[0]), "r"(a[1]), "r"(a[2]), "r"(a[3]), "r"(b[0]), "r"(b[1]));
}
#define CP16(saddr, gptr) \
    asm volatile("cp.async.cg.shared.global [%0], [%1], 16;" :: "r"(saddr), "l"(gptr))
#define CP_COMMIT() asm volatile("cp.async.commit_group;" ::: "memory")
#define CP_WAIT0()  asm volatile("cp.async.wait_group 0;" ::: "memory")

// ---------------- fused prepass: half_logits + normalize + qlab ----------------
__global__ __launch_bounds__(256) void prepass(
    const float* __restrict__ new_logits, const float* __restrict__ new_embeds,
    const int* __restrict__ ql, const int* __restrict__ labels,
    const int* __restrict__ hdrp)
{
    const int b = blockIdx.x, tid = threadIdx.x;
    if (b < 1024) {
        int idx = (b * 256 + tid) * 4;
        float4 v = *(const float4*)(new_logits + idx);
        __half2 h0 = __floats2half2_rn(v.x, v.y);
        __half2 h1 = __floats2half2_rn(v.z, v.w);
        uint2 p; p.x = *(uint32_t*)&h0; p.y = *(uint32_t*)&h1;
        *(uint2*)(g_a2 + idx) = p;
    } else if (b < 1152) {
        int i = b - 1024;
        const float* xr = new_embeds + (size_t)i * DDIM;
        float s = 0.f;
        for (int d = tid; d < DDIM; d += 256) { float v = xr[d]; s += v * v; }
        for (int o = 16; o; o >>= 1) s += __shfl_down_sync(0xffffffffu, s, o);
        __shared__ float sh[8];
        if ((tid & 31) == 0) sh[tid >> 5] = s;
        __syncthreads();
        __shared__ float invs;
        if (tid == 0) {
            float tot = 0.f;
            for (int w = 0; w < 8; w++) tot += sh[w];
            invs = 1.0f / fmaxf(sqrtf(tot), 1e-12f);
        }
        __syncthreads();
        float iv = invs;
        for (int d = tid; d < DDIM; d += 256)
            g_a1[i * DDIM + d] = __half_as_ushort(__float2half_rn(xr[d] * iv));
    } else {
        int j = (b - 1152) * 256 + tid;
        int hdr = *hdrp;
        int r = (j - hdr) & (NQ - 1);
        g_qlab[j] = (r < NROW) ? labels[r] : ql[j];
    }
}

// ---------------- fused fp16 GEMMs + register-light fused epilogue ----------------
// blocks [0,256):   l2 (K=CDIM) -> g_pp[1]
// blocks [256,512): l1 (K=DDIM) -> g_pp[0]
// CTA tile 128x128, BK=32; 8 warps (4M x 2N), warp tile 32x64.
constexpr int BPAD = 80;                 // fp16 tile row stride (conflict-free ldmatrix)
constexpr int FSTR = 144;                // fp32 staging row stride
constexpr int SZ_T = 128 * BPAD;         // 10240
constexpr int SZ_F = 128 * FSTR;         // 18432
constexpr int O_A   = 0;                 // [2 stages x 10240]
constexpr int O_B16 = 2 * SZ_T;          // 20480 [2 stages x 10240]
constexpr int O_FS  = 4 * SZ_T;          // 40960 [2 stages x 18432]
constexpr int GEMM_SMEM = O_FS + 2 * SZ_F;   // 77824 -> 2 CTAs/SM

__global__ __launch_bounds__(256, 2) void gemm_mma(
    const float* __restrict__ Bq2, const float* __restrict__ Bold2,
    const float* __restrict__ Bq1, const float* __restrict__ Bold1,  // feat_queue, old_embeds
    const int* __restrict__ labels,
    const int* __restrict__ hdrp)
{
    extern __shared__ char smem[];
    const uint32_t sb = smem_u32(smem);
    const int tid = threadIdx.x, lane = tid & 31, wid = tid >> 5;
    const int wm = wid >> 1, wn = wid & 1;
    const int bidx = blockIdx.x;

    // select problem (l2 long blocks first)
    const bool is2 = (bidx < 256);
    const int ctaN = is2 ? bidx : bidx - 256;
    const int n0 = ctaN * 128;
    const int K  = is2 ? CDIM : DDIM;
    const unsigned short* A = is2 ? g_a2 : g_a1;
    const float* Bq   = is2 ? Bq2 : Bq1;
    const float* Bold = is2 ? Bold2 : Bold1;
    const int nch = K >> 5;

    // B gmem row with circular-queue redirect; 2 threads per row, 64B (16 fp32) each
    const int rb = tid >> 1, seg = tid & 1;
    const int hdr = *hdrp;
    const int j = n0 + rb;
    const int r = (j - hdr) & (NQ - 1);
    const char* gB = (const char*)(((r < NROW) ? (Bold + (size_t)r * K)
                                               : (Bq + (size_t)j * K)) + seg * 16);

    // A: 2 threads per row, 32B each
    const int arow = tid >> 1;
    const int acol = (tid & 1) * 32;
    const char* gA = (const char*)A + (size_t)arow * K * 2 + acol;
    const uint32_t sA = sb + O_A + arow * BPAD + acol;

    // ldmatrix lane addressing
    const int g = lane >> 3, lr = lane & 7;
    const uint32_t aRowOff = (uint32_t)(wm * 32 + (g & 1) * 8 + lr) * BPAD + (g >> 1) * 16;
    const uint32_t bRowOff = (uint32_t)(wn * 64 + (g >> 1) * 8 + lr) * BPAD + (g & 1) * 16;

    float acc[2][8][4];
#pragma unroll
    for (int mt = 0; mt < 2; mt++)
#pragma unroll
        for (int nt = 0; nt < 8; nt++)
#pragma unroll
            for (int u = 0; u < 4; u++) acc[mt][nt][u] = 0.f;

    auto cpA = [&](int c, int st) {
        const char* s0 = gA + (size_t)c * 64;
        uint32_t d0 = sA + st * SZ_T;
        CP16(d0, s0); CP16(d0 + 16, s0 + 16);
    };
    auto cpB = [&](int c, int st) {
        const char* s0 = gB + (size_t)c * 128;
        uint32_t d0 = sb + O_FS + st * SZ_F + rb * FSTR + seg * 64;
#pragma unroll
        for (int i = 0; i < 4; i++) CP16(d0 + 16 * i, s0 + 16 * i);
    };
    auto convertB = [&](int st2) {
        const char* src = smem + O_FS + st2 * SZ_F + rb * FSTR + seg * 64;
        float4 f0 = *(const float4*)(src);
        float4 f1 = *(const float4*)(src + 16);
        float4 f2 = *(const float4*)(src + 32);
        float4 f3 = *(const float4*)(src + 48);
        __half2 h0 = __floats2half2_rn(f0.x, f0.y);
        __half2 h1 = __floats2half2_rn(f0.z, f0.w);
        __half2 h2 = __floats2half2_rn(f1.x, f1.y);
        __half2 h3 = __floats2half2_rn(f1.z, f1.w);
        __half2 h4 = __floats2half2_rn(f2.x, f2.y);
        __half2 h5 = __floats2half2_rn(f2.z, f2.w);
        __half2 h6 = __floats2half2_rn(f3.x, f3.y);
        __half2 h7 = __floats2half2_rn(f3.z, f3.w);
        uint4 p0, p1;
        p0.x = *(uint32_t*)&h0; p0.y = *(uint32_t*)&h1;
        p0.z = *(uint32_t*)&h2; p0.w = *(uint32_t*)&h3;
        p1.x = *(uint32_t*)&h4; p1.y = *(uint32_t*)&h5;
        p1.z = *(uint32_t*)&h6; p1.w = *(uint32_t*)&h7;
        char* d = smem + O_B16 + st2 * SZ_T + rb * BPAD + seg * 32;
        *(uint4*)d = p0;
        *(uint4*)(d + 16) = p1;
    };
    auto computeConv = [&](int c, bool conv) {
        const int st = c & 1;
        const uint32_t bA = sb + O_A + st * SZ_T + aRowOff;
        const uint32_t bB = sb + O_B16 + st * SZ_T + bRowOff;
        {   // ks = 0
            uint32_t a[2][4], b[4][4];
            ldm4(a[0], bA);
            ldm4(a[1], bA + 16 * BPAD);
#pragma unroll
            for (int p = 0; p < 4; p++) ldm4(b[p], bB + p * 16 * BPAD);
#pragma unroll
            for (int mt = 0; mt < 2; mt++)
#pragma unroll
                for (int nt = 0; nt < 8; nt++)
                    mma_f16(acc[mt][nt], a[mt], &b[nt >> 1][(nt & 1) * 2]);
        }
        if (conv) convertB(st ^ 1);
        {   // ks = 1
            uint32_t a[2][4], b[4][4];
            ldm4(a[0], bA + 32);
            ldm4(a[1], bA + 16 * BPAD + 32);
#pragma unroll
            for (int p = 0; p < 4; p++) ldm4(b[p], bB + p * 16 * BPAD + 32);
#pragma unroll
            for (int mt = 0; mt < 2; mt++)
#pragma unroll
                for (int nt = 0; nt < 8; nt++)
                    mma_f16(acc[mt][nt], a[mt], &b[nt >> 1][(nt & 1) * 2]);
        }
    };

    // ---- prologue ----
    cpB(0, 0);
    cpB(1, 1);
    cpA(0, 0);
    CP_COMMIT();
    CP_WAIT0();
    __syncthreads();
    convertB(0);
    __syncthreads();

    // ---- main loop ----
    for (int c = 0; c < nch; c++) {
        const int st = c & 1;
        if (c > 0) { CP_WAIT0(); __syncthreads(); }
        if (c + 2 < nch) cpB(c + 2, st);
        if (c + 1 < nch) cpA(c + 1, st ^ 1);
        CP_COMMIT();
        computeConv(c, c + 1 < nch);
    }

    // ===== fused epilogue (register-light): per-row LSE + masked sums =====
    __syncthreads();                       // compute done; smem reusable
    float* sred = (float*)smem;            // [128 rows][2 wn][8]
    const int qr = lane >> 2, qc = (lane & 3) * 2;

#pragma unroll
    for (int mt = 0; mt < 2; mt++) {
#pragma unroll
        for (int h = 0; h < 2; h++) {
            const int row = wm * 32 + mt * 16 + h * 8 + qr;
            const int lbl = labels[row];
            // quad max directly over acc
            float m = -INFINITY;
#pragma unroll
            for (int nt = 0; nt < 8; nt++)
                m = fmaxf(m, fmaxf(acc[mt][nt][2 * h], acc[mt][nt][2 * h + 1]));
            m = fmaxf(m, __shfl_xor_sync(0xffffffffu, m, 1));
            m = fmaxf(m, __shfl_xor_sync(0xffffffffu, m, 2));
            // sum exp + masked sums (qlab loaded inline; no big live arrays)
            float l = 0.f, sw = 0.f, s1 = 0.f, cn = 0.f;
#pragma unroll
            for (int nt = 0; nt < 8; nt++) {
#pragma unroll
                for (int u = 0; u < 2; u++) {
                    float v = acc[mt][nt][2 * h + u];
                    l += __expf(v - m);
                    const int col = n0 + wn * 64 + nt * 8 + qc + u;
                    if (g_qlab[col] == lbl) {
                        const int rr2 = (col - hdr) & (NQ - 1);
                        const float* frow = (rr2 < NROW) ? (Bold1 + (size_t)rr2 * DDIM)
                                                         : (Bq1 + (size_t)col * DDIM);
                        const float* oei = Bold1 + (size_t)row * DDIM;
                        float dot = 0.f;
#pragma unroll 8
                        for (int d = 0; d < DDIM; d++) dot = fmaf(oei[d], frow[d], dot);
                        float w = 0.5f * (dot + 1.0f);
                        sw += w; s1 += w * v; cn += 1.f;
                    }
                }
            }
            l  += __shfl_xor_sync(0xffffffffu, l, 1);
            l  += __shfl_xor_sync(0xffffffffu, l, 2);
            sw += __shfl_xor_sync(0xffffffffu, sw, 1);
            sw += __shfl_xor_sync(0xffffffffu, sw, 2);
            s1 += __shfl_xor_sync(0xffffffffu, s1, 1);
            s1 += __shfl_xor_sync(0xffffffffu, s1, 2);
            cn += __shfl_xor_sync(0xffffffffu, cn, 1);
            cn += __shfl_xor_sync(0xffffffffu, cn, 2);
            if ((lane & 3) == 0) {
                float* p = sred + (row * 2 + wn) * 8;
                p[0] = m; p[1] = l; p[2] = sw; p[3] = s1; p[4] = cn;
            }
        }
    }
    __syncthreads();
    if (tid < 128) {
        const float* p0 = sred + (tid * 2 + 0) * 8;
        const float* p1 = sred + (tid * 2 + 1) * 8;
        float M = fmaxf(p0[0], p1[0]);
        float L = p0[1] * __expf(p0[0] - M) + p1[1] * __expf(p1[0] - M);
        float4 a; a.x = M; a.y = L; a.z = p0[2] + p1[2]; a.w = p0[3] + p1[3];
        float4 b; b.x = p0[4] + p1[4]; b.y = 0.f; b.z = 0.f; b.w = 0.f;
        const int prob = is2 ? 1 : 0;
        *(float4*)&g_pp[prob][ctaN][tid][0] = a;
        *(float4*)&g_pp[prob][ctaN][tid][4] = b;
    }
}

// ---------------- merge: 256 partials per (prob,row) -> g_terms ----------------
__global__ __launch_bounds__(256) void merge_partials() {
    const int prob = blockIdx.x >> 7, row = blockIdx.x & 127, tid = threadIdx.x;
    float4 a = *(const float4*)&g_pp[prob][tid][row][0];
    float4 b = *(const float4*)&g_pp[prob][tid][row][4];
    float m = a.x, l = a.y, sw = a.z, s1 = a.w, cn = b.x;
    for (int o = 16; o; o >>= 1) {
        float mo = __shfl_down_sync(0xffffffffu, m, o);
        float lo = __shfl_down_sync(0xffffffffu, l, o);
        float nm = fmaxf(m, mo);
        l = l * __expf(m - nm) + lo * __expf(mo - nm);
        m = nm;
        sw += __shfl_down_sync(0xffffffffu, sw, o);
        s1 += __shfl_down_sync(0xffffffffu, s1, o);
        cn += __shfl_down_sync(0xffffffffu, cn, o);
    }
    __shared__ float shm[8], shl[8], shsw[8], shs1[8], shcn[8];
    if ((tid & 31) == 0) {
        int w = tid >> 5;
        shm[w] = m; shl[w] = l; shsw[w] = sw; shs1[w] = s1; shcn[w] = cn;
    }
    __syncthreads();
    if (tid == 0) {
        float M = shm[0], L = shl[0], SW = shsw[0], S1 = shs1[0], CN = shcn[0];
        for (int w = 1; w < 8; w++) {
            float nm = fmaxf(M, shm[w]);
            L = L * __expf(M - nm) + shl[w] * __expf(shm[w] - nm);
            M = nm;
            SW += shsw[w]; S1 += shs1[w]; CN += shcn[w];
        }
        float lse = M + logf(L);
        g_terms[prob * NROW + row] = (S1 - lse * SW) / CN;
    }
}

// ---------------- finalize ----------------
__global__ void finalize(float* __restrict__ out) {
    int tid = threadIdx.x;   // 128 threads, one row each
    float t1 = g_terms[tid];          // prob 0 = l1
    float t2 = g_terms[NROW + tid];   // prob 1 = l2
    for (int o = 16; o; o >>= 1) {
        t1 += __shfl_down_sync(0xffffffffu, t1, o);
        t2 += __shfl_down_sync(0xffffffffu, t2, o);
    }
    __shared__ float sh1[4], sh2[4];
    if ((tid & 31) == 0) { sh1[tid >> 5] = t1; sh2[tid >> 5] = t2; }
    __syncthreads();
    if (tid == 0) {
        out[0] = -(sh1[0] + sh1[1] + sh1[2] + sh1[3]) / (float)NROW;
        out[1] = -(sh2[0] + sh2[1] + sh2[2] + sh2[3]) / (float)NROW;
    }
}

// ---------------- launch ----------------
extern "C" void kernel_launch(void* const* d_in, const int* in_sizes, int n_in,
                              void* d_out, int out_size) {
    const float* old_embeds   = (const float*)d_in[0];
    const float* old_logits   = (const float*)d_in[1];
    const float* new_embeds   = (const float*)d_in[2];
    const float* new_logits   = (const float*)d_in[3];
    const int*   labels       = (const int*)d_in[4];
    const float* feat_queue   = (const float*)d_in[5];
    const float* logit_queue  = (const float*)d_in[6];
    const int*   queue_labels = (const int*)d_in[7];
    const int*   header       = (const int*)d_in[8];
    float* out = (float*)d_out;

    cudaFuncSetAttribute(gemm_mma, cudaFuncAttributeMaxDynamicSharedMemorySize, GEMM_SMEM);

    prepass<<<1280, 256>>>(new_logits, new_embeds, queue_labels, labels, header);

    // fused: [0,256) l2 (K=CDIM) -> g_pp[1], [256,512) l1 (K=DDIM) -> g_pp[0]
    gemm_mma<<<512, 256, GEMM_SMEM>>>(logit_queue, old_logits,
                                      feat_queue, old_embeds, labels, header);

    merge_partials<<<2 * NROW, 256>>>();
    finalize<<<1, 128>>>(out);
}